// round 1
// baseline (speedup 1.0000x reference)
#include <cuda_runtime.h>
#include <math.h>

#define BB 2048
#define SS 128
#define DD 128
#define HH 256
#define GG 1024  // 4*H

// ---------------- device scratch (allocation-free) ----------------
__device__ float g_h1[2][BB * HH];
__device__ float g_c1[BB * HH];
__device__ float g_h2[2][BB * HH];
__device__ float g_c2[BB * HH];
__device__ float g_din[BB * HH];
__device__ float g_decout[(size_t)BB * SS * HH];  // 256 MB

// reordered (gate-interleaved) weights: row' = 4*n + gate
__device__ float g_wx[4][GG * HH];   // input-side weights (enc0 uses only GG*DD)
__device__ float g_wh[4][GG * HH];   // hidden-side weights
__device__ float g_bias[4][GG];      // bih + bhh, reordered

__device__ __forceinline__ float* hsel(int s) {
    switch (s) {
        case 0: return g_h1[0];
        case 1: return g_h1[1];
        case 2: return g_h2[0];
        case 3: return g_h2[1];
        default: return g_din;
    }
}

// ---------------- weight reorder: dst[(4n+g)*K + k] = src[(g*H+n)*K + k] ----
__global__ void reorder_w(const float* __restrict__ src, int wsel, int which, int K) {
    int idx = blockIdx.x * blockDim.x + threadIdx.x;
    if (idx >= GG * K) return;
    int row = idx / K;
    int k = idx - row * K;
    int n = row >> 2, g = row & 3;
    float v = src[(g * HH + n) * K + k];
    if (which) g_wh[wsel][idx] = v;
    else       g_wx[wsel][idx] = v;
}

__global__ void reorder_b(const float* __restrict__ bih, const float* __restrict__ bhh, int wsel) {
    int r = blockIdx.x * blockDim.x + threadIdx.x;
    if (r < GG) {
        int n = r >> 2, g = r & 3;
        g_bias[wsel][r] = bih[g * HH + n] + bhh[g * HH + n];
    }
}

__global__ void zero_states() {
    int i = blockIdx.x * blockDim.x + threadIdx.x;
    if (i < BB * HH) {
        g_h1[0][i] = 0.f; g_c1[i] = 0.f;
        g_h2[0][i] = 0.f; g_c2[i] = 0.f;
        g_h1[1][i] = 0.f; g_h2[1][i] = 0.f;
    }
}

__global__ void save_encoded() {
    int i = blockIdx.x * blockDim.x + threadIdx.x;
    if (i < BB * HH) g_din[i] = g_h2[0][i];
}

// ---------------- fused LSTM cell: z = A1*W1^T + A2*W2^T + b, then gates ----
// Tile: 128(M) x 128(N), TK=16, 256 threads, 8x8 per-thread microtile.
// N columns are gate-interleaved: col = 4*unit + gate  -> epilogue owns full units.
__global__ __launch_bounds__(256, 1)
void lstm_cell(const float* __restrict__ xext, int a1_sel, int lda1, int K1,
               int wsel, int hread_sel, int hwrite_sel, int c_sel, int t_extra) {
    const float* A1 = (a1_sel < 0) ? xext : hsel(a1_sel);
    const float* A2 = hsel(hread_sel);              // [B x H], ld=HH
    const float* W1 = g_wx[wsel];                   // [GG x K1]
    const float* W2 = g_wh[wsel];                   // [GG x HH]
    const float* bias = g_bias[wsel];
    float* cbuf = c_sel ? g_c2 : g_c1;
    float* hout = hsel(hwrite_sel);
    float* hextra = (t_extra >= 0) ? (g_decout + (size_t)t_extra * HH) : nullptr;

    __shared__ float As[2][16][132];
    __shared__ float Bs[2][16][132];

    const int tid = threadIdx.x;
    const int tx = tid & 15, ty = tid >> 4;
    const int m0 = blockIdx.y * 128;
    const int n0 = blockIdx.x * 128;

    const int arow = tid >> 1;          // 0..127
    const int acol = (tid & 1) << 3;    // 0 or 8

    const int nk1 = K1 >> 4;
    const int ntiles = nk1 + (HH >> 4);

    const float* a1row = A1 + (size_t)(m0 + arow) * lda1 + acol;
    const float* w1row = W1 + (size_t)(n0 + arow) * K1 + acol;
    const float* a2row = A2 + (size_t)(m0 + arow) * HH + acol;
    const float* w2row = W2 + (size_t)(n0 + arow) * HH + acol;

    float acc[8][8];
#pragma unroll
    for (int i = 0; i < 8; i++)
#pragma unroll
        for (int j = 0; j < 8; j++) acc[i][j] = 0.f;

    // prologue: tile 0 -> buffer 0
    {
        const float* ap = a1row;  // t=0 always phase 1 (nk1 >= 1)
        const float* wp = w1row;
        float4 ra0 = *(const float4*)ap;
        float4 ra1 = *(const float4*)(ap + 4);
        float4 rb0 = *(const float4*)wp;
        float4 rb1 = *(const float4*)(wp + 4);
        float* sa = &As[0][acol][arow];
        float* sb = &Bs[0][acol][arow];
        sa[0*132]=ra0.x; sa[1*132]=ra0.y; sa[2*132]=ra0.z; sa[3*132]=ra0.w;
        sa[4*132]=ra1.x; sa[5*132]=ra1.y; sa[6*132]=ra1.z; sa[7*132]=ra1.w;
        sb[0*132]=rb0.x; sb[1*132]=rb0.y; sb[2*132]=rb0.z; sb[3*132]=rb0.w;
        sb[4*132]=rb1.x; sb[5*132]=rb1.y; sb[6*132]=rb1.z; sb[7*132]=rb1.w;
    }
    __syncthreads();

    for (int t = 0; t < ntiles; t++) {
        const int cur = t & 1;
        const bool more = (t + 1 < ntiles);
        float4 ra0, ra1, rb0, rb1;
        if (more) {
            int tn = t + 1;
            const float* ap;
            const float* wp;
            if (tn < nk1) { ap = a1row + tn * 16; wp = w1row + tn * 16; }
            else { int kk = (tn - nk1) * 16; ap = a2row + kk; wp = w2row + kk; }
            ra0 = *(const float4*)ap;
            ra1 = *(const float4*)(ap + 4);
            rb0 = *(const float4*)wp;
            rb1 = *(const float4*)(wp + 4);
        }
#pragma unroll
        for (int k = 0; k < 16; k++) {
            const float* as = &As[cur][k][0];
            const float* bs = &Bs[cur][k][0];
            float4 a0 = *(const float4*)(as + ty * 8);
            float4 a1 = *(const float4*)(as + ty * 8 + 4);
            float4 b0 = *(const float4*)(bs + tx * 8);
            float4 b1 = *(const float4*)(bs + tx * 8 + 4);
            float av[8] = {a0.x, a0.y, a0.z, a0.w, a1.x, a1.y, a1.z, a1.w};
            float bv[8] = {b0.x, b0.y, b0.z, b0.w, b1.x, b1.y, b1.z, b1.w};
#pragma unroll
            for (int i = 0; i < 8; i++)
#pragma unroll
                for (int j = 0; j < 8; j++) acc[i][j] += av[i] * bv[j];
        }
        if (more) {
            const int nxt = cur ^ 1;
            float* sa = &As[nxt][acol][arow];
            float* sb = &Bs[nxt][acol][arow];
            sa[0*132]=ra0.x; sa[1*132]=ra0.y; sa[2*132]=ra0.z; sa[3*132]=ra0.w;
            sa[4*132]=ra1.x; sa[5*132]=ra1.y; sa[6*132]=ra1.z; sa[7*132]=ra1.w;
            sb[0*132]=rb0.x; sb[1*132]=rb0.y; sb[2*132]=rb0.z; sb[3*132]=rb0.w;
            sb[4*132]=rb1.x; sb[5*132]=rb1.y; sb[6*132]=rb1.z; sb[7*132]=rb1.w;
        }
        __syncthreads();
    }

    // epilogue: gate-interleaved columns -> 2 full hidden units per thread
    const int colbase = n0 + tx * 8;
#pragma unroll
    for (int i = 0; i < 8; i++) {
        const int m = m0 + ty * 8 + i;
#pragma unroll
        for (int u = 0; u < 2; u++) {
            float zi = acc[i][4*u + 0] + bias[colbase + 4*u + 0];
            float zf = acc[i][4*u + 1] + bias[colbase + 4*u + 1];
            float zg = acc[i][4*u + 2] + bias[colbase + 4*u + 2];
            float zo = acc[i][4*u + 3] + bias[colbase + 4*u + 3];
            const int unit = (colbase >> 2) + u;
            float cold = cbuf[m * HH + unit];
            float ig = 1.f / (1.f + expf(-zi));
            float fg = 1.f / (1.f + expf(-zf));
            float gt = tanhf(zg);
            float og = 1.f / (1.f + expf(-zo));
            float cn = fg * cold + ig * gt;
            float hn = og * tanhf(cn);
            cbuf[m * HH + unit] = cn;
            hout[m * HH + unit] = hn;
            if (hextra) hextra[(size_t)m * (SS * HH) + unit] = hn;
        }
    }
}

// ---------------- output projection: out = decout @ Wout^T + bout ----------
// M = B*S (tiles of 128), N = D = 128 (one tile), K = H = 256.
__global__ __launch_bounds__(256, 1)
void out_proj(const float* __restrict__ W, const float* __restrict__ bout,
              float* __restrict__ out) {
    __shared__ float As[2][16][132];
    __shared__ float Bs[2][16][132];

    const int tid = threadIdx.x;
    const int tx = tid & 15, ty = tid >> 4;
    const int m0 = blockIdx.y * 128;

    const int arow = tid >> 1;
    const int acol = (tid & 1) << 3;
    const int ntiles = HH >> 4;  // 16

    const float* a0row = g_decout + (size_t)(m0 + arow) * HH + acol;
    const float* w0row = W + (size_t)arow * HH + acol;  // all 128 rows of Wout

    float acc[8][8];
#pragma unroll
    for (int i = 0; i < 8; i++)
#pragma unroll
        for (int j = 0; j < 8; j++) acc[i][j] = 0.f;

    {
        float4 ra0 = *(const float4*)a0row;
        float4 ra1 = *(const float4*)(a0row + 4);
        float4 rb0 = *(const float4*)w0row;
        float4 rb1 = *(const float4*)(w0row + 4);
        float* sa = &As[0][acol][arow];
        float* sb = &Bs[0][acol][arow];
        sa[0*132]=ra0.x; sa[1*132]=ra0.y; sa[2*132]=ra0.z; sa[3*132]=ra0.w;
        sa[4*132]=ra1.x; sa[5*132]=ra1.y; sa[6*132]=ra1.z; sa[7*132]=ra1.w;
        sb[0*132]=rb0.x; sb[1*132]=rb0.y; sb[2*132]=rb0.z; sb[3*132]=rb0.w;
        sb[4*132]=rb1.x; sb[5*132]=rb1.y; sb[6*132]=rb1.z; sb[7*132]=rb1.w;
    }
    __syncthreads();

    for (int t = 0; t < ntiles; t++) {
        const int cur = t & 1;
        const bool more = (t + 1 < ntiles);
        float4 ra0, ra1, rb0, rb1;
        if (more) {
            const float* ap = a0row + (t + 1) * 16;
            const float* wp = w0row + (t + 1) * 16;
            ra0 = *(const float4*)ap; ra1 = *(const float4*)(ap + 4);
            rb0 = *(const float4*)wp; rb1 = *(const float4*)(wp + 4);
        }
#pragma unroll
        for (int k = 0; k < 16; k++) {
            const float* as = &As[cur][k][0];
            const float* bs = &Bs[cur][k][0];
            float4 a0 = *(const float4*)(as + ty * 8);
            float4 a1 = *(const float4*)(as + ty * 8 + 4);
            float4 b0 = *(const float4*)(bs + tx * 8);
            float4 b1 = *(const float4*)(bs + tx * 8 + 4);
            float av[8] = {a0.x, a0.y, a0.z, a0.w, a1.x, a1.y, a1.z, a1.w};
            float bv[8] = {b0.x, b0.y, b0.z, b0.w, b1.x, b1.y, b1.z, b1.w};
#pragma unroll
            for (int i = 0; i < 8; i++)
#pragma unroll
                for (int j = 0; j < 8; j++) acc[i][j] += av[i] * bv[j];
        }
        if (more) {
            const int nxt = cur ^ 1;
            float* sa = &As[nxt][acol][arow];
            float* sb = &Bs[nxt][acol][arow];
            sa[0*132]=ra0.x; sa[1*132]=ra0.y; sa[2*132]=ra0.z; sa[3*132]=ra0.w;
            sa[4*132]=ra1.x; sa[5*132]=ra1.y; sa[6*132]=ra1.z; sa[7*132]=ra1.w;
            sb[0*132]=rb0.x; sb[1*132]=rb0.y; sb[2*132]=rb0.z; sb[3*132]=rb0.w;
            sb[4*132]=rb1.x; sb[5*132]=rb1.y; sb[6*132]=rb1.z; sb[7*132]=rb1.w;
        }
        __syncthreads();
    }

#pragma unroll
    for (int i = 0; i < 8; i++) {
        const int m = m0 + ty * 8 + i;
#pragma unroll
        for (int j = 0; j < 8; j++) {
            const int col = tx * 8 + j;
            out[(size_t)m * DD + col] = acc[i][j] + bout[col];
        }
    }
}

// ---------------- host-side orchestration ----------------------------------
extern "C" void kernel_launch(void* const* d_in, const int* in_sizes, int n_in,
                              void* d_out, int out_size) {
    (void)in_sizes; (void)n_in;
    const float* x = (const float*)d_in[0];

    // weight reorder (cheap; re-run every call for determinism)
    reorder_w<<<(GG * DD + 255) / 256, 256>>>((const float*)d_in[1], 0, 0, DD);
    reorder_w<<<(GG * HH + 255) / 256, 256>>>((const float*)d_in[2], 0, 1, HH);
    reorder_w<<<(GG * HH + 255) / 256, 256>>>((const float*)d_in[5], 1, 0, HH);
    reorder_w<<<(GG * HH + 255) / 256, 256>>>((const float*)d_in[6], 1, 1, HH);
    reorder_w<<<(GG * HH + 255) / 256, 256>>>((const float*)d_in[9], 2, 0, HH);
    reorder_w<<<(GG * HH + 255) / 256, 256>>>((const float*)d_in[10], 2, 1, HH);
    reorder_w<<<(GG * HH + 255) / 256, 256>>>((const float*)d_in[13], 3, 0, HH);
    reorder_w<<<(GG * HH + 255) / 256, 256>>>((const float*)d_in[14], 3, 1, HH);
    reorder_b<<<(GG + 255) / 256, 256>>>((const float*)d_in[3], (const float*)d_in[4], 0);
    reorder_b<<<(GG + 255) / 256, 256>>>((const float*)d_in[7], (const float*)d_in[8], 1);
    reorder_b<<<(GG + 255) / 256, 256>>>((const float*)d_in[11], (const float*)d_in[12], 2);
    reorder_b<<<(GG + 255) / 256, 256>>>((const float*)d_in[15], (const float*)d_in[16], 3);

    const int nst = (BB * HH + 255) / 256;
    zero_states<<<nst, 256>>>();

    dim3 grid(GG / 128, BB / 128);  // (8, 16)

    // ---- encoder ----
    for (int t = 0; t < SS; t++) {
        int p = t & 1;
        // layer 0: input x_t (ld = S*D), state h1/c1
        lstm_cell<<<grid, 256>>>(x + (size_t)t * DD, -1, SS * DD, DD,
                                 0, p, 1 - p, 0, -1);
        // layer 1: input new h1, state h2/c2
        lstm_cell<<<grid, 256>>>(nullptr, 1 - p, HH, HH,
                                 1, 2 + p, 2 + (1 - p), 1, -1);
    }
    // encoded = g_h2[0] (last write lands in buffer 0 for even S)
    save_encoded<<<nst, 256>>>();
    zero_states<<<nst, 256>>>();

    // ---- decoder (autoregressive) ----
    for (int t = 0; t < SS; t++) {
        int p = t & 1;
        int in_sel = (t == 0) ? 4 : (2 + p);  // din at t=0, else previous h2
        lstm_cell<<<grid, 256>>>(nullptr, in_sel, HH, HH,
                                 2, p, 1 - p, 0, -1);
        lstm_cell<<<grid, 256>>>(nullptr, 1 - p, HH, HH,
                                 3, 2 + p, 2 + (1 - p), 1, t);  // writes decout[:,t,:]
    }

    // ---- output projection ----
    out_proj<<<dim3(1, (BB * SS) / 128), 256>>>((const float*)d_in[17],
                                                (const float*)d_in[18],
                                                (float*)d_out);
}

// round 3
// speedup vs baseline: 1.3662x; 1.3662x over previous
#include <cuda_runtime.h>
#include <cuda_bf16.h>
#include <stdint.h>

#define BB 2048
#define SS 128
#define DD 128
#define HH 256
#define GG 1024  // 4*H

// ---------------- device scratch (allocation-free) ----------------
__device__ float g_c1[BB * HH];
__device__ float g_c2[BB * HH];
__device__ __nv_bfloat16 g_h1hi[2][BB * HH], g_h1lo[2][BB * HH];
__device__ __nv_bfloat16 g_h2hi[2][BB * HH], g_h2lo[2][BB * HH];
__device__ __nv_bfloat16 g_dinhi[BB * HH], g_dinlo[BB * HH];
__device__ __nv_bfloat16 g_xhi[(size_t)BB * SS * DD], g_xlo[(size_t)BB * SS * DD];
__device__ float g_decout[(size_t)BB * SS * HH];  // 256 MB

// gate-interleaved (row' = 4n+g) bf16 hi/lo weights
__device__ __nv_bfloat16 g_wxhi[4][GG * HH], g_wxlo[4][GG * HH];
__device__ __nv_bfloat16 g_whhi[4][GG * HH], g_whlo[4][GG * HH];
__device__ float g_bias[4][GG];

__device__ __forceinline__ __nv_bfloat16* hsel_hi(int s) {
    switch (s) {
        case 0: return g_h1hi[0];
        case 1: return g_h1hi[1];
        case 2: return g_h2hi[0];
        case 3: return g_h2hi[1];
        default: return g_dinhi;
    }
}
__device__ __forceinline__ __nv_bfloat16* hsel_lo(int s) {
    switch (s) {
        case 0: return g_h1lo[0];
        case 1: return g_h1lo[1];
        case 2: return g_h2lo[0];
        case 3: return g_h2lo[1];
        default: return g_dinlo;
    }
}

// ---------------- PTX helpers ----------------
__device__ __forceinline__ uint32_t smem_u32(const void* p) {
    uint32_t a;
    asm("{ .reg .u64 t; cvta.to.shared.u64 t, %1; cvt.u32.u64 %0, t; }" : "=r"(a) : "l"(p));
    return a;
}
#define CPA16(sm, g) asm volatile("cp.async.cg.shared.global [%0], [%1], 16;" :: "r"(sm), "l"(g) : "memory")
#define CP_COMMIT()  asm volatile("cp.async.commit_group;" ::: "memory")
#define CP_WAIT1()   asm volatile("cp.async.wait_group 1;" ::: "memory")
#define CP_WAIT0()   asm volatile("cp.async.wait_group 0;" ::: "memory")
#define LDSM4(r0, r1, r2, r3, a) \
    asm volatile("ldmatrix.sync.aligned.m8n8.x4.shared.b16 {%0,%1,%2,%3}, [%4];" \
        : "=r"(r0), "=r"(r1), "=r"(r2), "=r"(r3) : "r"(a))
#define MMA16816(d, a, b0, b1) \
    asm volatile("mma.sync.aligned.m16n8k16.row.col.f32.bf16.bf16.f32 " \
        "{%0,%1,%2,%3},{%4,%5,%6,%7},{%8,%9},{%0,%1,%2,%3};" \
        : "+f"((d)[0]), "+f"((d)[1]), "+f"((d)[2]), "+f"((d)[3]) \
        : "r"((a)[0]), "r"((a)[1]), "r"((a)[2]), "r"((a)[3]), "r"(b0), "r"(b1))

__device__ __forceinline__ float sigf(float x) {
    return __fdividef(1.f, 1.f + __expf(-x));
}
__device__ __forceinline__ float tanhv(float x) {
    return 2.f * sigf(2.f * x) - 1.f;
}

// ---------------- conversion / setup kernels ----------------
__global__ void conv_x(const float* __restrict__ x) {
    size_t i = (size_t)blockIdx.x * blockDim.x + threadIdx.x;
    if (i < (size_t)BB * SS * DD) {
        float v = x[i];
        __nv_bfloat16 hi = __float2bfloat16_rn(v);
        g_xhi[i] = hi;
        g_xlo[i] = __float2bfloat16_rn(v - __bfloat162float(hi));
    }
}

__global__ void reorder_w_split(const float* __restrict__ src, int wsel, int which, int K) {
    int idx = blockIdx.x * blockDim.x + threadIdx.x;
    if (idx >= GG * K) return;
    int row = idx / K;
    int k = idx - row * K;
    int n = row >> 2, g = row & 3;
    float v = src[(g * HH + n) * K + k];
    __nv_bfloat16 hi = __float2bfloat16_rn(v);
    __nv_bfloat16 lo = __float2bfloat16_rn(v - __bfloat162float(hi));
    if (which) { g_whhi[wsel][idx] = hi; g_whlo[wsel][idx] = lo; }
    else       { g_wxhi[wsel][idx] = hi; g_wxlo[wsel][idx] = lo; }
}

__global__ void reorder_b(const float* __restrict__ bih, const float* __restrict__ bhh, int wsel) {
    int r = blockIdx.x * blockDim.x + threadIdx.x;
    if (r < GG) {
        int n = r >> 2, g = r & 3;
        g_bias[wsel][r] = bih[g * HH + n] + bhh[g * HH + n];
    }
}

__global__ void zero_states() {
    int i = blockIdx.x * blockDim.x + threadIdx.x;
    if (i < BB * HH) {
        __nv_bfloat16 z = __float2bfloat16(0.f);
        g_c1[i] = 0.f; g_c2[i] = 0.f;
        g_h1hi[0][i] = z; g_h1lo[0][i] = z; g_h1hi[1][i] = z; g_h1lo[1][i] = z;
        g_h2hi[0][i] = z; g_h2lo[0][i] = z; g_h2hi[1][i] = z; g_h2lo[1][i] = z;
    }
}

__global__ void save_encoded() {
    int i = blockIdx.x * blockDim.x + threadIdx.x;
    if (i < BB * HH) { g_dinhi[i] = g_h2hi[0][i]; g_dinlo[i] = g_h2lo[0][i]; }
}

// ---------------- mma.sync fused LSTM cell ----------------
// z[2048,1024] = A1*W1^T + A2*W2^T (+bias) with bf16 hi/lo 3-pass split.
// CTA 128x128, 8 warps (4M x 2N), warp tile 32x64, K-chunk 32, cp.async 2-stage.
// SMEM per buffer: 4 arrays x 128 rows x 80B (32 bf16 + 8 pad) = 40960B; x2 = 81920B.
#define ROWB 80
#define ARR_STRIDE 10240
#define BUF_STRIDE 40960

__global__ __launch_bounds__(256, 1)
void lstm_cell_mma(int a1_sel, int t, int K1, int wsel,
                   int hread_sel, int hwrite_sel, int c_sel, int t_extra) {
    extern __shared__ char sm[];
    const uint32_t smu = smem_u32(sm);

    const int tid = threadIdx.x;
    const int lane = tid & 31, wid = tid >> 5;
    const int m0 = blockIdx.y * 128;
    const int n0 = blockIdx.x * 128;
    const int wm = (wid & 3) * 32;   // warp M offset within CTA tile
    const int wn = (wid >> 2) * 64;  // warp N offset within CTA tile

    // ---- source pointers ----
    const __nv_bfloat16 *A1h, *A1l;
    size_t ldA1b;
    if (a1_sel < 0) {
        A1h = g_xhi + (size_t)t * DD; A1l = g_xlo + (size_t)t * DD;
        ldA1b = (size_t)SS * DD * 2;
    } else {
        A1h = hsel_hi(a1_sel); A1l = hsel_lo(a1_sel); ldA1b = HH * 2;
    }
    const char* bA1h = (const char*)A1h + (size_t)m0 * ldA1b;
    const char* bA1l = (const char*)A1l + (size_t)m0 * ldA1b;
    const char* bA2h = (const char*)hsel_hi(hread_sel) + (size_t)m0 * HH * 2;
    const char* bA2l = (const char*)hsel_lo(hread_sel) + (size_t)m0 * HH * 2;
    const char* bW1h = (const char*)g_wxhi[wsel] + (size_t)n0 * K1 * 2;
    const char* bW1l = (const char*)g_wxlo[wsel] + (size_t)n0 * K1 * 2;
    const char* bW2h = (const char*)g_whhi[wsel] + (size_t)n0 * HH * 2;
    const char* bW2l = (const char*)g_whlo[wsel] + (size_t)n0 * HH * 2;

    const int nk1c = K1 >> 5;                 // A1 chunks (4 or 8)
    const int ns = nk1c + (HH >> 5);          // total chunks (12 or 16)

    // ---- per-thread ldmatrix smem offsets (within array) ----
    uint32_t aoff[2];
#pragma unroll
    for (int mt = 0; mt < 2; mt++)
        aoff[mt] = (uint32_t)(wm + mt * 16 + (lane & 15)) * ROWB + ((lane >> 4) * 16);
    uint32_t woff[4];
#pragma unroll
    for (int j2 = 0; j2 < 4; j2++)
        woff[j2] = (uint32_t)(wn + (j2 * 2 + (lane >> 4)) * 8 + (lane & 7)) * ROWB
                 + (((lane >> 3) & 1) * 16);

    float acc[2][8][4];
#pragma unroll
    for (int mt = 0; mt < 2; mt++)
#pragma unroll
        for (int j = 0; j < 8; j++)
#pragma unroll
            for (int r = 0; r < 4; r++) acc[mt][j][r] = 0.f;

    // ---- copy issuer ----
    auto issue = [&](int cs, int buf) {
        const char *sAh, *sAl, *sWh, *sWl;
        size_t ldAb, ldWb, kb;
        if (cs < nk1c) {
            kb = (size_t)cs * 64;
            ldAb = ldA1b; ldWb = (size_t)K1 * 2;
            sAh = bA1h + kb; sAl = bA1l + kb; sWh = bW1h + kb; sWl = bW1l + kb;
        } else {
            kb = (size_t)(cs - nk1c) * 64;
            ldAb = HH * 2; ldWb = HH * 2;
            sAh = bA2h + kb; sAl = bA2l + kb; sWh = bW2h + kb; sWl = bW2l + kb;
        }
        const uint32_t sb = smu + buf * BUF_STRIDE;
#pragma unroll
        for (int it = 0; it < 2; it++) {
            const int i = tid + (it << 8);
            const int row = i >> 2;
            const uint32_t cb = (uint32_t)(i & 3) * 16;
            const uint32_t so = (uint32_t)row * ROWB + cb;
            CPA16(sb + 0 * ARR_STRIDE + so, sAh + (size_t)row * ldAb + cb);
            CPA16(sb + 1 * ARR_STRIDE + so, sAl + (size_t)row * ldAb + cb);
            CPA16(sb + 2 * ARR_STRIDE + so, sWh + (size_t)row * ldWb + cb);
            CPA16(sb + 3 * ARR_STRIDE + so, sWl + (size_t)row * ldWb + cb);
        }
        CP_COMMIT();
    };

    issue(0, 0);

    for (int s = 0; s < ns; s++) {
        if (s + 1 < ns) { issue(s + 1, (s + 1) & 1); CP_WAIT1(); }
        else            { CP_WAIT0(); }
        __syncthreads();

        const uint32_t base = smu + (s & 1) * BUF_STRIDE;
#pragma unroll
        for (int ks = 0; ks < 2; ks++) {
            uint32_t ah[2][4], al[2][4];
#pragma unroll
            for (int mt = 0; mt < 2; mt++) {
                const uint32_t ad = base + aoff[mt] + ks * 32;
                LDSM4(ah[mt][0], ah[mt][1], ah[mt][2], ah[mt][3], ad);
                LDSM4(al[mt][0], al[mt][1], al[mt][2], al[mt][3], ad + ARR_STRIDE);
            }
            uint32_t wh[16], wl[16];
#pragma unroll
            for (int j2 = 0; j2 < 4; j2++) {
                const uint32_t wd = base + 2 * ARR_STRIDE + woff[j2] + ks * 32;
                LDSM4(wh[4*j2+0], wh[4*j2+1], wh[4*j2+2], wh[4*j2+3], wd);
                LDSM4(wl[4*j2+0], wl[4*j2+1], wl[4*j2+2], wl[4*j2+3], wd + ARR_STRIDE);
            }
#pragma unroll
            for (int mt = 0; mt < 2; mt++)
#pragma unroll
                for (int j = 0; j < 8; j++)
                    MMA16816(acc[mt][j], ah[mt], wh[2*j], wh[2*j+1]);
#pragma unroll
            for (int mt = 0; mt < 2; mt++)
#pragma unroll
                for (int j = 0; j < 8; j++)
                    MMA16816(acc[mt][j], al[mt], wh[2*j], wh[2*j+1]);
#pragma unroll
            for (int mt = 0; mt < 2; mt++)
#pragma unroll
                for (int j = 0; j < 8; j++)
                    MMA16816(acc[mt][j], ah[mt], wl[2*j], wl[2*j+1]);
        }
        __syncthreads();
    }

    // ---------------- epilogue: gates straight from accumulators ----------------
    // Fragment: c0,c1 = (row g, cols 2q,2q+1), c2,c3 = (row g+8, same cols).
    // Thread pair (q even, q odd) holds (i,f) / (g,o) of the same unit; a
    // shfl.xor(1) swap gives each thread one full unit: even -> row g, odd -> row g+8.
    const float* bias = g_bias[wsel];
    float* cbase = c_sel ? g_c2 : g_c1;
    __nv_bfloat16* hh = hsel_hi(hwrite_sel);
    __nv_bfloat16* hl = hsel_lo(hwrite_sel);
    const int q = lane & 3, p = q & 1, g = lane >> 2;

#pragma unroll
    for (int mt = 0; mt < 2; mt++) {
#pragma unroll
        for (int j = 0; j < 8; j++) {
            float c0 = acc[mt][j][0], c1 = acc[mt][j][1];
            float c2 = acc[mt][j][2], c3 = acc[mt][j][3];
            float e0 = __shfl_xor_sync(0xffffffffu, c0, 1);
            float e1 = __shfl_xor_sync(0xffffffffu, c1, 1);
            float e2 = __shfl_xor_sync(0xffffffffu, c2, 1);
            float e3 = __shfl_xor_sync(0xffffffffu, c3, 1);
            const int row = m0 + wm + mt * 16 + g + (p ? 8 : 0);
            const int col = n0 + wn + j * 8 + (q >> 1) * 4;
            float zi, zf, zg, zo;
            if (!p) { zi = c0; zf = c1; zg = e0; zo = e1; }
            else    { zi = e2; zf = e3; zg = c2; zo = c3; }
            zi += bias[col];     zf += bias[col + 1];
            zg += bias[col + 2]; zo += bias[col + 3];
            const int un = col >> 2;
            const size_t si = (size_t)row * HH + un;
            float cold = cbase[si];
            float ig = sigf(zi), fg = sigf(zf), og = sigf(zo);
            float gt = tanhv(zg);
            float cn = fg * cold + ig * gt;
            float hn = og * tanhv(cn);
            cbase[si] = cn;
            __nv_bfloat16 hib = __float2bfloat16_rn(hn);
            hh[si] = hib;
            hl[si] = __float2bfloat16_rn(hn - __bfloat162float(hib));
            if (t_extra >= 0)
                g_decout[(size_t)row * (SS * HH) + (size_t)t_extra * HH + un] = hn;
        }
    }
}

// ---------------- output projection: out = decout @ Wout^T + bout ----------
__global__ __launch_bounds__(256, 1)
void out_proj(const float* __restrict__ W, const float* __restrict__ bout,
              float* __restrict__ out) {
    __shared__ float As[2][16][132];
    __shared__ float Bs[2][16][132];

    const int tid = threadIdx.x;
    const int tx = tid & 15, ty = tid >> 4;
    const int m0 = blockIdx.y * 128;

    const int arow = tid >> 1;
    const int acol = (tid & 1) << 3;
    const int ntiles = HH >> 4;  // 16

    const float* a0row = g_decout + (size_t)(m0 + arow) * HH + acol;
    const float* w0row = W + (size_t)arow * HH + acol;

    float acc[8][8];
#pragma unroll
    for (int i = 0; i < 8; i++)
#pragma unroll
        for (int j = 0; j < 8; j++) acc[i][j] = 0.f;

    {
        float4 ra0 = *(const float4*)a0row;
        float4 ra1 = *(const float4*)(a0row + 4);
        float4 rb0 = *(const float4*)w0row;
        float4 rb1 = *(const float4*)(w0row + 4);
        float* sa = &As[0][acol][arow];
        float* sb = &Bs[0][acol][arow];
        sa[0*132]=ra0.x; sa[1*132]=ra0.y; sa[2*132]=ra0.z; sa[3*132]=ra0.w;
        sa[4*132]=ra1.x; sa[5*132]=ra1.y; sa[6*132]=ra1.z; sa[7*132]=ra1.w;
        sb[0*132]=rb0.x; sb[1*132]=rb0.y; sb[2*132]=rb0.z; sb[3*132]=rb0.w;
        sb[4*132]=rb1.x; sb[5*132]=rb1.y; sb[6*132]=rb1.z; sb[7*132]=rb1.w;
    }
    __syncthreads();

    for (int t = 0; t < ntiles; t++) {
        const int cur = t & 1;
        const bool more = (t + 1 < ntiles);
        float4 ra0, ra1, rb0, rb1;
        if (more) {
            const float* ap = a0row + (t + 1) * 16;
            const float* wp = w0row + (t + 1) * 16;
            ra0 = *(const float4*)ap; ra1 = *(const float4*)(ap + 4);
            rb0 = *(const float4*)wp; rb1 = *(const float4*)(wp + 4);
        }
#pragma unroll
        for (int k = 0; k < 16; k++) {
            const float* as = &As[cur][k][0];
            const float* bs = &Bs[cur][k][0];
            float4 a0 = *(const float4*)(as + ty * 8);
            float4 a1 = *(const float4*)(as + ty * 8 + 4);
            float4 b0 = *(const float4*)(bs + tx * 8);
            float4 b1 = *(const float4*)(bs + tx * 8 + 4);
            float av[8] = {a0.x, a0.y, a0.z, a0.w, a1.x, a1.y, a1.z, a1.w};
            float bv[8] = {b0.x, b0.y, b0.z, b0.w, b1.x, b1.y, b1.z, b1.w};
#pragma unroll
            for (int i = 0; i < 8; i++)
#pragma unroll
                for (int j = 0; j < 8; j++) acc[i][j] += av[i] * bv[j];
        }
        if (more) {
            const int nxt = cur ^ 1;
            float* sa = &As[nxt][acol][arow];
            float* sb = &Bs[nxt][acol][arow];
            sa[0*132]=ra0.x; sa[1*132]=ra0.y; sa[2*132]=ra0.z; sa[3*132]=ra0.w;
            sa[4*132]=ra1.x; sa[5*132]=ra1.y; sa[6*132]=ra1.z; sa[7*132]=ra1.w;
            sb[0*132]=rb0.x; sb[1*132]=rb0.y; sb[2*132]=rb0.z; sb[3*132]=rb0.w;
            sb[4*132]=rb1.x; sb[5*132]=rb1.y; sb[6*132]=rb1.z; sb[7*132]=rb1.w;
        }
        __syncthreads();
    }

#pragma unroll
    for (int i = 0; i < 8; i++) {
        const int m = m0 + ty * 8 + i;
#pragma unroll
        for (int j = 0; j < 8; j++) {
            const int col = tx * 8 + j;
            out[(size_t)m * DD + col] = acc[i][j] + bout[col];
        }
    }
}

// ---------------- host-side orchestration ----------------------------------
extern "C" void kernel_launch(void* const* d_in, const int* in_sizes, int n_in,
                              void* d_out, int out_size) {
    (void)in_sizes; (void)n_in; (void)out_size;
    const float* x = (const float*)d_in[0];

    static const int SMEM_DYN = 2 * BUF_STRIDE;  // 81920
    cudaFuncSetAttribute(lstm_cell_mma, cudaFuncAttributeMaxDynamicSharedMemorySize, SMEM_DYN);

    conv_x<<<(int)(((size_t)BB * SS * DD + 255) / 256), 256>>>(x);
    reorder_w_split<<<(GG * DD + 255) / 256, 256>>>((const float*)d_in[1], 0, 0, DD);
    reorder_w_split<<<(GG * HH + 255) / 256, 256>>>((const float*)d_in[2], 0, 1, HH);
    reorder_w_split<<<(GG * HH + 255) / 256, 256>>>((const float*)d_in[5], 1, 0, HH);
    reorder_w_split<<<(GG * HH + 255) / 256, 256>>>((const float*)d_in[6], 1, 1, HH);
    reorder_w_split<<<(GG * HH + 255) / 256, 256>>>((const float*)d_in[9], 2, 0, HH);
    reorder_w_split<<<(GG * HH + 255) / 256, 256>>>((const float*)d_in[10], 2, 1, HH);
    reorder_w_split<<<(GG * HH + 255) / 256, 256>>>((const float*)d_in[13], 3, 0, HH);
    reorder_w_split<<<(GG * HH + 255) / 256, 256>>>((const float*)d_in[14], 3, 1, HH);
    reorder_b<<<(GG + 255) / 256, 256>>>((const float*)d_in[3], (const float*)d_in[4], 0);
    reorder_b<<<(GG + 255) / 256, 256>>>((const float*)d_in[7], (const float*)d_in[8], 1);
    reorder_b<<<(GG + 255) / 256, 256>>>((const float*)d_in[11], (const float*)d_in[12], 2);
    reorder_b<<<(GG + 255) / 256, 256>>>((const float*)d_in[15], (const float*)d_in[16], 3);

    const int nst = (BB * HH + 255) / 256;
    zero_states<<<nst, 256>>>();

    dim3 grid(GG / 128, BB / 128);  // (8, 16)

    // ---- encoder ----
    for (int t = 0; t < SS; t++) {
        int p = t & 1;
        lstm_cell_mma<<<grid, 256, SMEM_DYN>>>(-1, t, DD, 0, p, 1 - p, 0, -1);
        lstm_cell_mma<<<grid, 256, SMEM_DYN>>>(1 - p, 0, HH, 1, 2 + p, 2 + (1 - p), 1, -1);
    }
    save_encoded<<<nst, 256>>>();
    zero_states<<<nst, 256>>>();

    // ---- decoder (autoregressive) ----
    for (int t = 0; t < SS; t++) {
        int p = t & 1;
        int in_sel = (t == 0) ? 4 : (2 + p);
        lstm_cell_mma<<<grid, 256, SMEM_DYN>>>(in_sel, 0, HH, 2, p, 1 - p, 0, -1);
        lstm_cell_mma<<<grid, 256, SMEM_DYN>>>(1 - p, 0, HH, 3, 2 + p, 2 + (1 - p), 1, t);
    }

    // ---- output projection ----
    out_proj<<<dim3(1, (BB * SS) / 128), 256>>>((const float*)d_in[17],
                                                (const float*)d_in[18],
                                                (float*)d_out);
}

// round 4
// speedup vs baseline: 1.6749x; 1.2259x over previous
#include <cuda_runtime.h>
#include <cuda_fp16.h>
#include <stdint.h>

#define BB 2048
#define SS 128
#define DD 128
#define HH 256
#define GG 1024  // 4*H

// ---------------- device scratch (allocation-free) ----------------
__device__ float g_c1[BB * HH];
__device__ float g_c2[BB * HH];
__device__ __half g_h1hi[2][BB * HH], g_h1lo[2][BB * HH];
__device__ __half g_h2hi[2][BB * HH], g_h2lo[2][BB * HH];
__device__ __half g_dinhi[BB * HH], g_dinlo[BB * HH];
__device__ __half g_xhi[(size_t)BB * SS * DD], g_xlo[(size_t)BB * SS * DD];
__device__ float g_decout[(size_t)BB * SS * HH];  // 256 MB

// gate-interleaved (row' = 4n+g) fp16 weights (single precision level)
__device__ __half g_wx[4][GG * HH];
__device__ __half g_wh[4][GG * HH];
__device__ float g_bias[4][GG];

__device__ __forceinline__ __half* hsel_hi(int s) {
    switch (s) {
        case 0: return g_h1hi[0];
        case 1: return g_h1hi[1];
        case 2: return g_h2hi[0];
        case 3: return g_h2hi[1];
        default: return g_dinhi;
    }
}
__device__ __forceinline__ __half* hsel_lo(int s) {
    switch (s) {
        case 0: return g_h1lo[0];
        case 1: return g_h1lo[1];
        case 2: return g_h2lo[0];
        case 3: return g_h2lo[1];
        default: return g_dinlo;
    }
}

// ---------------- PTX helpers ----------------
__device__ __forceinline__ uint32_t smem_u32(const void* p) {
    uint32_t a;
    asm("{ .reg .u64 t; cvta.to.shared.u64 t, %1; cvt.u32.u64 %0, t; }" : "=r"(a) : "l"(p));
    return a;
}
#define CPA16(sm, g) asm volatile("cp.async.cg.shared.global [%0], [%1], 16;" :: "r"(sm), "l"(g) : "memory")
#define CP_COMMIT()  asm volatile("cp.async.commit_group;" ::: "memory")
#define CP_WAIT1()   asm volatile("cp.async.wait_group 1;" ::: "memory")
#define CP_WAIT0()   asm volatile("cp.async.wait_group 0;" ::: "memory")
#define LDSM4(r0, r1, r2, r3, a) \
    asm volatile("ldmatrix.sync.aligned.m8n8.x4.shared.b16 {%0,%1,%2,%3}, [%4];" \
        : "=r"(r0), "=r"(r1), "=r"(r2), "=r"(r3) : "r"(a))
#define MMA16816(d, a, b0, b1) \
    asm volatile("mma.sync.aligned.m16n8k16.row.col.f32.f16.f16.f32 " \
        "{%0,%1,%2,%3},{%4,%5,%6,%7},{%8,%9},{%0,%1,%2,%3};" \
        : "+f"((d)[0]), "+f"((d)[1]), "+f"((d)[2]), "+f"((d)[3]) \
        : "r"((a)[0]), "r"((a)[1]), "r"((a)[2]), "r"((a)[3]), "r"(b0), "r"(b1))

__device__ __forceinline__ float sigf(float x) {
    return __fdividef(1.f, 1.f + __expf(-x));
}
__device__ __forceinline__ float tanhv(float x) {
    return 2.f * sigf(2.f * x) - 1.f;
}

// ---------------- setup kernels ----------------
__global__ void conv_x(const float* __restrict__ x) {
    size_t i = (size_t)blockIdx.x * blockDim.x + threadIdx.x;
    if (i < (size_t)BB * SS * DD) {
        float v = x[i];
        __half hi = __float2half_rn(v);
        g_xhi[i] = hi;
        g_xlo[i] = __float2half_rn(v - __half2float(hi));
    }
}

// All weight/bias prep in ONE kernel (y = 0..7 weights, y = 8 biases)
__global__ void setup_weights(
    const float* w0, const float* w1, const float* w2, const float* w3,
    const float* w4, const float* w5, const float* w6, const float* w7,
    const float* b0a, const float* b0b, const float* b1a, const float* b1b,
    const float* b2a, const float* b2b, const float* b3a, const float* b3b) {
    const int y = blockIdx.y;
    const int idx = blockIdx.x * blockDim.x + threadIdx.x;
    if (y < 8) {
        const int wsel = y >> 1, which = y & 1;
        const int K = (y == 0) ? DD : HH;
        if (idx >= GG * K) return;
        const float* srcs[8] = {w0, w1, w2, w3, w4, w5, w6, w7};
        const float* src = srcs[y];
        int row = idx / K;
        int k = idx - row * K;
        int n = row >> 2, g = row & 3;
        __half v = __float2half_rn(src[(g * HH + n) * K + k]);
        if (which) g_wh[wsel][idx] = v;
        else       g_wx[wsel][idx] = v;
    } else {
        if (idx >= 4 * GG) return;
        const int wsel = idx >> 10;        // /GG
        const int r = idx & (GG - 1);
        const float* bihs[4] = {b0a, b1a, b2a, b3a};
        const float* bhhs[4] = {b0b, b1b, b2b, b3b};
        int n = r >> 2, g = r & 3;
        g_bias[wsel][r] = bihs[wsel][g * HH + n] + bhhs[wsel][g * HH + n];
    }
}

__global__ void zero_states() {
    int i = blockIdx.x * blockDim.x + threadIdx.x;
    if (i < BB * HH) {
        __half z = __float2half(0.f);
        g_c1[i] = 0.f; g_c2[i] = 0.f;
        g_h1hi[0][i] = z; g_h1lo[0][i] = z; g_h1hi[1][i] = z; g_h1lo[1][i] = z;
        g_h2hi[0][i] = z; g_h2lo[0][i] = z; g_h2hi[1][i] = z; g_h2lo[1][i] = z;
    }
}

__global__ void save_encoded() {
    int i = blockIdx.x * blockDim.x + threadIdx.x;
    if (i < BB * HH) { g_dinhi[i] = g_h2hi[0][i]; g_dinlo[i] = g_h2lo[0][i]; }
}

// ---------------- mma.sync fused LSTM cell (fp16, 2-pass) ----------------
// z[2048,1024] = A1*W1^T + A2*W2^T (+bias); A split fp16 hi/lo, W single fp16.
// CTA 128x128, 8 warps (4M x 2N), warp tile 32x64, K-chunk 32, 3-stage cp.async.
// SMEM per stage: 3 arrays x 128 rows x 80B = 30720B; x3 stages = 92160B.
#define ROWB 80
#define ARR_STRIDE 10240
#define BUF_STRIDE 30720

__global__ __launch_bounds__(256, 1)
void lstm_cell_mma(int a1_sel, int t, int K1, int wsel,
                   int hread_sel, int hwrite_sel, int c_sel, int t_extra) {
    extern __shared__ char sm[];
    const uint32_t smu = smem_u32(sm);

    const int tid = threadIdx.x;
    const int lane = tid & 31, wid = tid >> 5;
    const int m0 = blockIdx.y * 128;
    const int n0 = blockIdx.x * 128;
    const int wm = (wid & 3) * 32;
    const int wn = (wid >> 2) * 64;

    // ---- source pointers ----
    const __half *A1h, *A1l;
    size_t ldA1b;
    if (a1_sel < 0) {
        A1h = g_xhi + (size_t)t * DD; A1l = g_xlo + (size_t)t * DD;
        ldA1b = (size_t)SS * DD * 2;
    } else {
        A1h = hsel_hi(a1_sel); A1l = hsel_lo(a1_sel); ldA1b = HH * 2;
    }
    const char* bA1h = (const char*)A1h + (size_t)m0 * ldA1b;
    const char* bA1l = (const char*)A1l + (size_t)m0 * ldA1b;
    const char* bA2h = (const char*)hsel_hi(hread_sel) + (size_t)m0 * HH * 2;
    const char* bA2l = (const char*)hsel_lo(hread_sel) + (size_t)m0 * HH * 2;
    const char* bW1 = (const char*)g_wx[wsel] + (size_t)n0 * K1 * 2;
    const char* bW2 = (const char*)g_wh[wsel] + (size_t)n0 * HH * 2;

    const int nk1c = K1 >> 5;                 // A1 chunks (4 or 8)
    const int ns = nk1c + (HH >> 5);          // total chunks (12 or 16)

    // ---- ldmatrix per-thread smem offsets (within array) ----
    uint32_t aoff[2];
#pragma unroll
    for (int mt = 0; mt < 2; mt++)
        aoff[mt] = (uint32_t)(wm + mt * 16 + (lane & 15)) * ROWB + ((lane >> 4) * 16);
    uint32_t woff[4];
#pragma unroll
    for (int j2 = 0; j2 < 4; j2++)
        woff[j2] = (uint32_t)(wn + (j2 * 2 + (lane >> 4)) * 8 + (lane & 7)) * ROWB
                 + (((lane >> 3) & 1) * 16);

    float acc[2][8][4];
#pragma unroll
    for (int mt = 0; mt < 2; mt++)
#pragma unroll
        for (int j = 0; j < 8; j++)
#pragma unroll
            for (int r = 0; r < 4; r++) acc[mt][j][r] = 0.f;

    auto issue = [&](int cs, int buf) {
        const char *sAh, *sAl, *sW;
        size_t ldAb, ldWb, kb;
        if (cs < nk1c) {
            kb = (size_t)cs * 64;
            ldAb = ldA1b; ldWb = (size_t)K1 * 2;
            sAh = bA1h + kb; sAl = bA1l + kb; sW = bW1 + kb;
        } else {
            kb = (size_t)(cs - nk1c) * 64;
            ldAb = HH * 2; ldWb = HH * 2;
            sAh = bA2h + kb; sAl = bA2l + kb; sW = bW2 + kb;
        }
        const uint32_t sb = smu + buf * BUF_STRIDE;
#pragma unroll
        for (int it = 0; it < 2; it++) {
            const int i = tid + (it << 8);
            const int row = i >> 2;
            const uint32_t cb = (uint32_t)(i & 3) * 16;
            const uint32_t so = (uint32_t)row * ROWB + cb;
            CPA16(sb + 0 * ARR_STRIDE + so, sAh + (size_t)row * ldAb + cb);
            CPA16(sb + 1 * ARR_STRIDE + so, sAl + (size_t)row * ldAb + cb);
            CPA16(sb + 2 * ARR_STRIDE + so, sW + (size_t)row * ldWb + cb);
        }
        CP_COMMIT();
    };

    issue(0, 0);
    issue(1, 1);

    int buf = 0;
    for (int s = 0; s < ns; s++) {
        if (s == ns - 1) CP_WAIT0();
        else             CP_WAIT1();
        __syncthreads();

        const uint32_t base = smu + buf * BUF_STRIDE;
#pragma unroll
        for (int ks = 0; ks < 2; ks++) {
            uint32_t ah[2][4], al[2][4];
#pragma unroll
            for (int mt = 0; mt < 2; mt++) {
                const uint32_t ad = base + aoff[mt] + ks * 32;
                LDSM4(ah[mt][0], ah[mt][1], ah[mt][2], ah[mt][3], ad);
                LDSM4(al[mt][0], al[mt][1], al[mt][2], al[mt][3], ad + ARR_STRIDE);
            }
            uint32_t w[16];
#pragma unroll
            for (int j2 = 0; j2 < 4; j2++) {
                const uint32_t wd = base + 2 * ARR_STRIDE + woff[j2] + ks * 32;
                LDSM4(w[4*j2+0], w[4*j2+1], w[4*j2+2], w[4*j2+3], wd);
            }
#pragma unroll
            for (int mt = 0; mt < 2; mt++)
#pragma unroll
                for (int j = 0; j < 8; j++)
                    MMA16816(acc[mt][j], ah[mt], w[2*j], w[2*j+1]);
#pragma unroll
            for (int mt = 0; mt < 2; mt++)
#pragma unroll
                for (int j = 0; j < 8; j++)
                    MMA16816(acc[mt][j], al[mt], w[2*j], w[2*j+1]);
        }
        if (s + 2 < ns) issue(s + 2, (buf + 2) % 3);
        buf = (buf + 1) % 3;
    }

    // ---------------- epilogue: gates straight from accumulators ----------------
    const float* bias = g_bias[wsel];
    float* cbase = c_sel ? g_c2 : g_c1;
    __half* hh = hsel_hi(hwrite_sel);
    __half* hl = hsel_lo(hwrite_sel);
    const int q = lane & 3, p = q & 1, g = lane >> 2;

#pragma unroll
    for (int mt = 0; mt < 2; mt++) {
#pragma unroll
        for (int j = 0; j < 8; j++) {
            float c0 = acc[mt][j][0], c1 = acc[mt][j][1];
            float c2 = acc[mt][j][2], c3 = acc[mt][j][3];
            float e0 = __shfl_xor_sync(0xffffffffu, c0, 1);
            float e1 = __shfl_xor_sync(0xffffffffu, c1, 1);
            float e2 = __shfl_xor_sync(0xffffffffu, c2, 1);
            float e3 = __shfl_xor_sync(0xffffffffu, c3, 1);
            const int row = m0 + wm + mt * 16 + g + (p ? 8 : 0);
            const int col = n0 + wn + j * 8 + (q >> 1) * 4;
            float zi, zf, zg, zo;
            if (!p) { zi = c0; zf = c1; zg = e0; zo = e1; }
            else    { zi = e2; zf = e3; zg = c2; zo = c3; }
            zi += bias[col];     zf += bias[col + 1];
            zg += bias[col + 2]; zo += bias[col + 3];
            const int un = col >> 2;
            const size_t si = (size_t)row * HH + un;
            float cold = cbase[si];
            float ig = sigf(zi), fg = sigf(zf), og = sigf(zo);
            float gt = tanhv(zg);
            float cn = fg * cold + ig * gt;
            float hn = og * tanhv(cn);
            cbase[si] = cn;
            __half hib = __float2half_rn(hn);
            hh[si] = hib;
            hl[si] = __float2half_rn(hn - __half2float(hib));
            if (t_extra >= 0)
                g_decout[(size_t)row * (SS * HH) + (size_t)t_extra * HH + un] = hn;
        }
    }
}

// ---------------- output projection: out = decout @ Wout^T + bout ----------
__global__ __launch_bounds__(256, 1)
void out_proj(const float* __restrict__ W, const float* __restrict__ bout,
              float* __restrict__ out) {
    __shared__ float As[2][16][132];
    __shared__ float Bs[2][16][132];

    const int tid = threadIdx.x;
    const int tx = tid & 15, ty = tid >> 4;
    const int m0 = blockIdx.y * 128;

    const int arow = tid >> 1;
    const int acol = (tid & 1) << 3;
    const int ntiles = HH >> 4;  // 16

    const float* a0row = g_decout + (size_t)(m0 + arow) * HH + acol;
    const float* w0row = W + (size_t)arow * HH + acol;

    float acc[8][8];
#pragma unroll
    for (int i = 0; i < 8; i++)
#pragma unroll
        for (int j = 0; j < 8; j++) acc[i][j] = 0.f;

    {
        float4 ra0 = *(const float4*)a0row;
        float4 ra1 = *(const float4*)(a0row + 4);
        float4 rb0 = *(const float4*)w0row;
        float4 rb1 = *(const float4*)(w0row + 4);
        float* sa = &As[0][acol][arow];
        float* sb = &Bs[0][acol][arow];
        sa[0*132]=ra0.x; sa[1*132]=ra0.y; sa[2*132]=ra0.z; sa[3*132]=ra0.w;
        sa[4*132]=ra1.x; sa[5*132]=ra1.y; sa[6*132]=ra1.z; sa[7*132]=ra1.w;
        sb[0*132]=rb0.x; sb[1*132]=rb0.y; sb[2*132]=rb0.z; sb[3*132]=rb0.w;
        sb[4*132]=rb1.x; sb[5*132]=rb1.y; sb[6*132]=rb1.z; sb[7*132]=rb1.w;
    }
    __syncthreads();

    for (int t = 0; t < ntiles; t++) {
        const int cur = t & 1;
        const bool more = (t + 1 < ntiles);
        float4 ra0, ra1, rb0, rb1;
        if (more) {
            const float* ap = a0row + (t + 1) * 16;
            const float* wp = w0row + (t + 1) * 16;
            ra0 = *(const float4*)ap; ra1 = *(const float4*)(ap + 4);
            rb0 = *(const float4*)wp; rb1 = *(const float4*)(wp + 4);
        }
#pragma unroll
        for (int k = 0; k < 16; k++) {
            const float* as = &As[cur][k][0];
            const float* bs = &Bs[cur][k][0];
            float4 a0 = *(const float4*)(as + ty * 8);
            float4 a1 = *(const float4*)(as + ty * 8 + 4);
            float4 b0 = *(const float4*)(bs + tx * 8);
            float4 b1 = *(const float4*)(bs + tx * 8 + 4);
            float av[8] = {a0.x, a0.y, a0.z, a0.w, a1.x, a1.y, a1.z, a1.w};
            float bv[8] = {b0.x, b0.y, b0.z, b0.w, b1.x, b1.y, b1.z, b1.w};
#pragma unroll
            for (int i = 0; i < 8; i++)
#pragma unroll
                for (int j = 0; j < 8; j++) acc[i][j] += av[i] * bv[j];
        }
        if (more) {
            const int nxt = cur ^ 1;
            float* sa = &As[nxt][acol][arow];
            float* sb = &Bs[nxt][acol][arow];
            sa[0*132]=ra0.x; sa[1*132]=ra0.y; sa[2*132]=ra0.z; sa[3*132]=ra0.w;
            sa[4*132]=ra1.x; sa[5*132]=ra1.y; sa[6*132]=ra1.z; sa[7*132]=ra1.w;
            sb[0*132]=rb0.x; sb[1*132]=rb0.y; sb[2*132]=rb0.z; sb[3*132]=rb0.w;
            sb[4*132]=rb1.x; sb[5*132]=rb1.y; sb[6*132]=rb1.z; sb[7*132]=rb1.w;
        }
        __syncthreads();
    }

#pragma unroll
    for (int i = 0; i < 8; i++) {
        const int m = m0 + ty * 8 + i;
#pragma unroll
        for (int j = 0; j < 8; j++) {
            const int col = tx * 8 + j;
            out[(size_t)m * DD + col] = acc[i][j] + bout[col];
        }
    }
}

// ---------------- host-side orchestration ----------------------------------
extern "C" void kernel_launch(void* const* d_in, const int* in_sizes, int n_in,
                              void* d_out, int out_size) {
    (void)in_sizes; (void)n_in; (void)out_size;
    const float* x = (const float*)d_in[0];

    static const int SMEM_DYN = 3 * BUF_STRIDE;  // 92160
    cudaFuncSetAttribute(lstm_cell_mma, cudaFuncAttributeMaxDynamicSharedMemorySize, SMEM_DYN);

    // launch 1: x conversion
    conv_x<<<(int)(((size_t)BB * SS * DD + 255) / 256), 256>>>(x);
    // launch 2: all weights + biases
    setup_weights<<<dim3((GG * HH + 255) / 256, 9), 256>>>(
        (const float*)d_in[1], (const float*)d_in[2],
        (const float*)d_in[5], (const float*)d_in[6],
        (const float*)d_in[9], (const float*)d_in[10],
        (const float*)d_in[13], (const float*)d_in[14],
        (const float*)d_in[3], (const float*)d_in[4],
        (const float*)d_in[7], (const float*)d_in[8],
        (const float*)d_in[11], (const float*)d_in[12],
        (const float*)d_in[15], (const float*)d_in[16]);

    const int nst = (BB * HH + 255) / 256;
    // launch 3: zero states
    zero_states<<<nst, 256>>>();

    dim3 grid(GG / 128, BB / 128);  // (8, 16)

    // ---- encoder ---- (launches 4.. : ncu -s 5 -c 1 now catches a cell)
    for (int t = 0; t < SS; t++) {
        int p = t & 1;
        lstm_cell_mma<<<grid, 256, SMEM_DYN>>>(-1, t, DD, 0, p, 1 - p, 0, -1);
        lstm_cell_mma<<<grid, 256, SMEM_DYN>>>(1 - p, 0, HH, 1, 2 + p, 2 + (1 - p), 1, -1);
    }
    save_encoded<<<nst, 256>>>();
    zero_states<<<nst, 256>>>();

    // ---- decoder (autoregressive) ----
    for (int t = 0; t < SS; t++) {
        int p = t & 1;
        int in_sel = (t == 0) ? 4 : (2 + p);
        lstm_cell_mma<<<grid, 256, SMEM_DYN>>>(in_sel, 0, HH, 2, p, 1 - p, 0, -1);
        lstm_cell_mma<<<grid, 256, SMEM_DYN>>>(1 - p, 0, HH, 3, 2 + p, 2 + (1 - p), 1, t);
    }

    // ---- output projection ----
    out_proj<<<dim3(1, (BB * SS) / 128), 256>>>((const float*)d_in[17],
                                                (const float*)d_in[18],
                                                (float*)d_out);
}

// round 5
// speedup vs baseline: 1.9382x; 1.1572x over previous
#include <cuda_runtime.h>
#include <cuda_fp16.h>
#include <stdint.h>

#define BB 2048
#define SS 128
#define DD 128
#define HH 256
#define GG 1024  // 4*H

// ---------------- device scratch (allocation-free) ----------------
__device__ float g_c1[BB * HH];
__device__ float g_c2[BB * HH];
__device__ __half g_h1[2][BB * HH];
__device__ __half g_h2[2][BB * HH];
__device__ __half g_din[BB * HH];
__device__ __half g_x[(size_t)BB * SS * DD];
__device__ float g_decout[(size_t)BB * SS * HH];  // 256 MB

// gate-interleaved (row' = 4n+g) fp16 weights
__device__ __half g_wx[4][GG * HH];
__device__ __half g_wh[4][GG * HH];
__device__ float g_bias[4][GG];

__device__ __forceinline__ __half* hsel(int s) {
    switch (s) {
        case 0: return g_h1[0];
        case 1: return g_h1[1];
        case 2: return g_h2[0];
        case 3: return g_h2[1];
        default: return g_din;
    }
}

// ---------------- PTX helpers ----------------
__device__ __forceinline__ uint32_t smem_u32(const void* p) {
    uint32_t a;
    asm("{ .reg .u64 t; cvta.to.shared.u64 t, %1; cvt.u32.u64 %0, t; }" : "=r"(a) : "l"(p));
    return a;
}
#define CPA16(sm, g) asm volatile("cp.async.cg.shared.global [%0], [%1], 16;" :: "r"(sm), "l"(g) : "memory")
#define CP_COMMIT()  asm volatile("cp.async.commit_group;" ::: "memory")
#define CP_WAIT2()   asm volatile("cp.async.wait_group 2;" ::: "memory")
#define CP_WAIT1()   asm volatile("cp.async.wait_group 1;" ::: "memory")
#define CP_WAIT0()   asm volatile("cp.async.wait_group 0;" ::: "memory")
#define LDSM4(r0, r1, r2, r3, a) \
    asm volatile("ldmatrix.sync.aligned.m8n8.x4.shared.b16 {%0,%1,%2,%3}, [%4];" \
        : "=r"(r0), "=r"(r1), "=r"(r2), "=r"(r3) : "r"(a))
#define MMA16816(d, a, b0, b1) \
    asm volatile("mma.sync.aligned.m16n8k16.row.col.f32.f16.f16.f32 " \
        "{%0,%1,%2,%3},{%4,%5,%6,%7},{%8,%9},{%0,%1,%2,%3};" \
        : "+f"((d)[0]), "+f"((d)[1]), "+f"((d)[2]), "+f"((d)[3]) \
        : "r"((a)[0]), "r"((a)[1]), "r"((a)[2]), "r"((a)[3]), "r"(b0), "r"(b1))

__device__ __forceinline__ float sigf(float x) {
    return __fdividef(1.f, 1.f + __expf(-x));
}
__device__ __forceinline__ float tanhv(float x) {
    return 2.f * sigf(2.f * x) - 1.f;
}

// ---------------- setup kernels ----------------
__global__ void conv_x(const float* __restrict__ x) {
    size_t i = (size_t)blockIdx.x * blockDim.x + threadIdx.x;
    if (i < (size_t)BB * SS * DD) g_x[i] = __float2half_rn(x[i]);
}

__global__ void setup_weights(
    const float* w0, const float* w1, const float* w2, const float* w3,
    const float* w4, const float* w5, const float* w6, const float* w7,
    const float* b0a, const float* b0b, const float* b1a, const float* b1b,
    const float* b2a, const float* b2b, const float* b3a, const float* b3b) {
    const int y = blockIdx.y;
    const int idx = blockIdx.x * blockDim.x + threadIdx.x;
    if (y < 8) {
        const int wsel = y >> 1, which = y & 1;
        const int K = (y == 0) ? DD : HH;
        if (idx >= GG * K) return;
        const float* srcs[8] = {w0, w1, w2, w3, w4, w5, w6, w7};
        const float* src = srcs[y];
        int row = idx / K;
        int k = idx - row * K;
        int n = row >> 2, g = row & 3;
        __half v = __float2half_rn(src[(g * HH + n) * K + k]);
        if (which) g_wh[wsel][idx] = v;
        else       g_wx[wsel][idx] = v;
    } else {
        if (idx >= 4 * GG) return;
        const int wsel = idx >> 10;
        const int r = idx & (GG - 1);
        const float* bihs[4] = {b0a, b1a, b2a, b3a};
        const float* bhhs[4] = {b0b, b1b, b2b, b3b};
        int n = r >> 2, g = r & 3;
        g_bias[wsel][r] = bihs[wsel][g * HH + n] + bhhs[wsel][g * HH + n];
    }
}

__global__ void zero_states() {
    int i = blockIdx.x * blockDim.x + threadIdx.x;
    if (i < BB * HH) {
        __half z = __float2half(0.f);
        g_c1[i] = 0.f; g_c2[i] = 0.f;
        g_h1[0][i] = z; g_h1[1][i] = z;
        g_h2[0][i] = z; g_h2[1][i] = z;
    }
}

__global__ void save_encoded() {
    int i = blockIdx.x * blockDim.x + threadIdx.x;
    if (i < BB * HH) g_din[i] = g_h2[0][i];
}

// ---------------- mma.sync fused LSTM cell (fp16, single-pass) ----------------
// z[2048,1024] = A1*W1^T + A2*W2^T (+bias); everything fp16 in, fp32 accum.
// CTA 64(M) x 128(N), 8 warps (2M x 4N), warp tile 32x32, K-chunk 32,
// 4-stage cp.async. SMEM/stage: A 64x80 + W 128x80 = 15360B; x4 = 61440B.
#define ROWB 80
#define A_BYTES 5120
#define BUF_STRIDE 15360

__global__ __launch_bounds__(256, 2)
void lstm_cell_mma(int a1_sel, int t, int K1, int wsel,
                   int hread_sel, int hwrite_sel, int c_sel, int t_extra) {
    extern __shared__ char sm[];
    const uint32_t smu = smem_u32(sm);

    const int tid = threadIdx.x;
    const int lane = tid & 31, wid = tid >> 5;
    const int m0 = blockIdx.y * 64;
    const int n0 = blockIdx.x * 128;
    const int wm = (wid & 1) * 32;   // warp M offset (2 warps in M)
    const int wn = (wid >> 1) * 32;  // warp N offset (4 warps in N)

    // ---- source pointers ----
    const __half* A1;
    size_t ldA1b;
    if (a1_sel < 0) {
        A1 = g_x + (size_t)t * DD;
        ldA1b = (size_t)SS * DD * 2;
    } else {
        A1 = hsel(a1_sel); ldA1b = HH * 2;
    }
    const char* bA1 = (const char*)A1 + (size_t)m0 * ldA1b;
    const char* bA2 = (const char*)hsel(hread_sel) + (size_t)m0 * HH * 2;
    const char* bW1 = (const char*)g_wx[wsel] + (size_t)n0 * K1 * 2;
    const char* bW2 = (const char*)g_wh[wsel] + (size_t)n0 * HH * 2;

    const int nk1c = K1 >> 5;                 // A1 chunks (4 or 8)
    const int ns = nk1c + (HH >> 5);          // total (12 or 16)

    // ---- ldmatrix per-thread smem offsets ----
    uint32_t aoff[2];
#pragma unroll
    for (int mt = 0; mt < 2; mt++)
        aoff[mt] = (uint32_t)(wm + mt * 16 + (lane & 15)) * ROWB + ((lane >> 4) * 16);
    uint32_t woff[2];
#pragma unroll
    for (int j2 = 0; j2 < 2; j2++)
        woff[j2] = (uint32_t)(wn + (j2 * 2 + (lane >> 4)) * 8 + (lane & 7)) * ROWB
                 + (((lane >> 3) & 1) * 16);

    float acc[2][4][4];
#pragma unroll
    for (int mt = 0; mt < 2; mt++)
#pragma unroll
        for (int j = 0; j < 4; j++)
#pragma unroll
            for (int r = 0; r < 4; r++) acc[mt][j][r] = 0.f;

    auto issue = [&](int cs, int buf) {
        const char *sA, *sW;
        size_t ldAb, ldWb, kb;
        if (cs < nk1c) {
            kb = (size_t)cs * 64;
            ldAb = ldA1b; ldWb = (size_t)K1 * 2;
            sA = bA1 + kb; sW = bW1 + kb;
        } else {
            kb = (size_t)(cs - nk1c) * 64;
            ldAb = HH * 2; ldWb = HH * 2;
            sA = bA2 + kb; sW = bW2 + kb;
        }
        const uint32_t sb = smu + buf * BUF_STRIDE;
        // A: 64 rows x 64B -> 256 cp.async (1/thread)
        {
            const int row = tid >> 2;
            const uint32_t cb = (uint32_t)(tid & 3) * 16;
            CPA16(sb + (uint32_t)row * ROWB + cb, sA + (size_t)row * ldAb + cb);
        }
        // W: 128 rows x 64B -> 512 cp.async (2/thread)
#pragma unroll
        for (int it = 0; it < 2; it++) {
            const int f = tid + (it << 8);
            const int row = f >> 2;
            const uint32_t cb = (uint32_t)(f & 3) * 16;
            CPA16(sb + A_BYTES + (uint32_t)row * ROWB + cb, sW + (size_t)row * ldWb + cb);
        }
        CP_COMMIT();
    };

    issue(0, 0);
    issue(1, 1);
    issue(2, 2);

    for (int s = 0; s < ns; s++) {
        if (s + 2 < ns)      CP_WAIT2();
        else if (s + 1 < ns) CP_WAIT1();
        else                 CP_WAIT0();
        __syncthreads();

        const uint32_t base = smu + (s & 3) * BUF_STRIDE;
#pragma unroll
        for (int ks = 0; ks < 2; ks++) {
            uint32_t a[2][4];
#pragma unroll
            for (int mt = 0; mt < 2; mt++)
                LDSM4(a[mt][0], a[mt][1], a[mt][2], a[mt][3], base + aoff[mt] + ks * 32);
            uint32_t w[8];
#pragma unroll
            for (int j2 = 0; j2 < 2; j2++) {
                const uint32_t wd = base + A_BYTES + woff[j2] + ks * 32;
                LDSM4(w[4*j2+0], w[4*j2+1], w[4*j2+2], w[4*j2+3], wd);
            }
#pragma unroll
            for (int mt = 0; mt < 2; mt++)
#pragma unroll
                for (int j = 0; j < 4; j++)
                    MMA16816(acc[mt][j], a[mt], w[2*j], w[2*j+1]);
        }
        if (s + 3 < ns) issue(s + 3, (s + 3) & 3);
    }

    // ---------------- epilogue: gates from accumulators ----------------
    // Fragment: thread pair (q even/odd) swaps halves via shfl.xor(1) so each
    // thread owns one full (i,f,g,o) unit: even -> row g, odd -> row g+8.
    const float* bias = g_bias[wsel];
    float* cbase = c_sel ? g_c2 : g_c1;
    __half* hout = hsel(hwrite_sel);
    const int q = lane & 3, p = q & 1, g = lane >> 2;

#pragma unroll
    for (int mt = 0; mt < 2; mt++) {
#pragma unroll
        for (int j = 0; j < 4; j++) {
            float c0 = acc[mt][j][0], c1 = acc[mt][j][1];
            float c2 = acc[mt][j][2], c3 = acc[mt][j][3];
            float e0 = __shfl_xor_sync(0xffffffffu, c0, 1);
            float e1 = __shfl_xor_sync(0xffffffffu, c1, 1);
            float e2 = __shfl_xor_sync(0xffffffffu, c2, 1);
            float e3 = __shfl_xor_sync(0xffffffffu, c3, 1);
            const int row = m0 + wm + mt * 16 + g + (p ? 8 : 0);
            const int col = n0 + wn + j * 8 + (q >> 1) * 4;
            float zi, zf, zg, zo;
            if (!p) { zi = c0; zf = c1; zg = e0; zo = e1; }
            else    { zi = e2; zf = e3; zg = c2; zo = c3; }
            zi += bias[col];     zf += bias[col + 1];
            zg += bias[col + 2]; zo += bias[col + 3];
            const int un = col >> 2;
            const size_t si = (size_t)row * HH + un;
            float cold = cbase[si];
            float ig = sigf(zi), fg = sigf(zf), og = sigf(zo);
            float gt = tanhv(zg);
            float cn = fg * cold + ig * gt;
            float hn = og * tanhv(cn);
            cbase[si] = cn;
            hout[si] = __float2half_rn(hn);
            if (t_extra >= 0)
                g_decout[(size_t)row * (SS * HH) + (size_t)t_extra * HH + un] = hn;
        }
    }
}

// ---------------- output projection: out = decout @ Wout^T + bout ----------
__global__ __launch_bounds__(256, 1)
void out_proj(const float* __restrict__ W, const float* __restrict__ bout,
              float* __restrict__ out) {
    __shared__ float As[2][16][132];
    __shared__ float Bs[2][16][132];

    const int tid = threadIdx.x;
    const int tx = tid & 15, ty = tid >> 4;
    const int m0 = blockIdx.y * 128;

    const int arow = tid >> 1;
    const int acol = (tid & 1) << 3;
    const int ntiles = HH >> 4;  // 16

    const float* a0row = g_decout + (size_t)(m0 + arow) * HH + acol;
    const float* w0row = W + (size_t)arow * HH + acol;

    float acc[8][8];
#pragma unroll
    for (int i = 0; i < 8; i++)
#pragma unroll
        for (int j = 0; j < 8; j++) acc[i][j] = 0.f;

    {
        float4 ra0 = *(const float4*)a0row;
        float4 ra1 = *(const float4*)(a0row + 4);
        float4 rb0 = *(const float4*)w0row;
        float4 rb1 = *(const float4*)(w0row + 4);
        float* sa = &As[0][acol][arow];
        float* sb = &Bs[0][acol][arow];
        sa[0*132]=ra0.x; sa[1*132]=ra0.y; sa[2*132]=ra0.z; sa[3*132]=ra0.w;
        sa[4*132]=ra1.x; sa[5*132]=ra1.y; sa[6*132]=ra1.z; sa[7*132]=ra1.w;
        sb[0*132]=rb0.x; sb[1*132]=rb0.y; sb[2*132]=rb0.z; sb[3*132]=rb0.w;
        sb[4*132]=rb1.x; sb[5*132]=rb1.y; sb[6*132]=rb1.z; sb[7*132]=rb1.w;
    }
    __syncthreads();

    for (int t = 0; t < ntiles; t++) {
        const int cur = t & 1;
        const bool more = (t + 1 < ntiles);
        float4 ra0, ra1, rb0, rb1;
        if (more) {
            const float* ap = a0row + (t + 1) * 16;
            const float* wp = w0row + (t + 1) * 16;
            ra0 = *(const float4*)ap; ra1 = *(const float4*)(ap + 4);
            rb0 = *(const float4*)wp; rb1 = *(const float4*)(wp + 4);
        }
#pragma unroll
        for (int k = 0; k < 16; k++) {
            const float* as = &As[cur][k][0];
            const float* bs = &Bs[cur][k][0];
            float4 a0 = *(const float4*)(as + ty * 8);
            float4 a1 = *(const float4*)(as + ty * 8 + 4);
            float4 b0 = *(const float4*)(bs + tx * 8);
            float4 b1 = *(const float4*)(bs + tx * 8 + 4);
            float av[8] = {a0.x, a0.y, a0.z, a0.w, a1.x, a1.y, a1.z, a1.w};
            float bv[8] = {b0.x, b0.y, b0.z, b0.w, b1.x, b1.y, b1.z, b1.w};
#pragma unroll
            for (int i = 0; i < 8; i++)
#pragma unroll
                for (int j = 0; j < 8; j++) acc[i][j] += av[i] * bv[j];
        }
        if (more) {
            const int nxt = cur ^ 1;
            float* sa = &As[nxt][acol][arow];
            float* sb = &Bs[nxt][acol][arow];
            sa[0*132]=ra0.x; sa[1*132]=ra0.y; sa[2*132]=ra0.z; sa[3*132]=ra0.w;
            sa[4*132]=ra1.x; sa[5*132]=ra1.y; sa[6*132]=ra1.z; sa[7*132]=ra1.w;
            sb[0*132]=rb0.x; sb[1*132]=rb0.y; sb[2*132]=rb0.z; sb[3*132]=rb0.w;
            sb[4*132]=rb1.x; sb[5*132]=rb1.y; sb[6*132]=rb1.z; sb[7*132]=rb1.w;
        }
        __syncthreads();
    }

#pragma unroll
    for (int i = 0; i < 8; i++) {
        const int m = m0 + ty * 8 + i;
#pragma unroll
        for (int j = 0; j < 8; j++) {
            const int col = tx * 8 + j;
            out[(size_t)m * DD + col] = acc[i][j] + bout[col];
        }
    }
}

// ---------------- host-side orchestration ----------------------------------
extern "C" void kernel_launch(void* const* d_in, const int* in_sizes, int n_in,
                              void* d_out, int out_size) {
    (void)in_sizes; (void)n_in; (void)out_size;
    const float* x = (const float*)d_in[0];

    static const int SMEM_DYN = 4 * BUF_STRIDE;  // 61440
    cudaFuncSetAttribute(lstm_cell_mma, cudaFuncAttributeMaxDynamicSharedMemorySize, SMEM_DYN);

    conv_x<<<(int)(((size_t)BB * SS * DD + 255) / 256), 256>>>(x);
    setup_weights<<<dim3((GG * HH + 255) / 256, 9), 256>>>(
        (const float*)d_in[1], (const float*)d_in[2],
        (const float*)d_in[5], (const float*)d_in[6],
        (const float*)d_in[9], (const float*)d_in[10],
        (const float*)d_in[13], (const float*)d_in[14],
        (const float*)d_in[3], (const float*)d_in[4],
        (const float*)d_in[7], (const float*)d_in[8],
        (const float*)d_in[11], (const float*)d_in[12],
        (const float*)d_in[15], (const float*)d_in[16]);

    const int nst = (BB * HH + 255) / 256;
    zero_states<<<nst, 256>>>();

    dim3 grid(GG / 128, BB / 64);  // (8, 32) = 256 CTAs, one resident wave

    // ---- encoder ----
    for (int t = 0; t < SS; t++) {
        int p = t & 1;
        lstm_cell_mma<<<grid, 256, SMEM_DYN>>>(-1, t, DD, 0, p, 1 - p, 0, -1);
        lstm_cell_mma<<<grid, 256, SMEM_DYN>>>(1 - p, 0, HH, 1, 2 + p, 2 + (1 - p), 1, -1);
    }
    save_encoded<<<nst, 256>>>();
    zero_states<<<nst, 256>>>();

    // ---- decoder (autoregressive) ----
    for (int t = 0; t < SS; t++) {
        int p = t & 1;
        int in_sel = (t == 0) ? 4 : (2 + p);
        lstm_cell_mma<<<grid, 256, SMEM_DYN>>>(in_sel, 0, HH, 2, p, 1 - p, 0, -1);
        lstm_cell_mma<<<grid, 256, SMEM_DYN>>>(1 - p, 0, HH, 3, 2 + p, 2 + (1 - p), 1, t);
    }

    // ---- output projection ----
    out_proj<<<dim3(1, (BB * SS) / 128), 256>>>((const float*)d_in[17],
                                                (const float*)d_in[18],
                                                (float*)d_out);
}